// round 17
// baseline (speedup 1.0000x reference)
#include <cuda_runtime.h>
#include <stdint.h>

// DiceFromLabelsLoss: joint-histogram, fused persistent kernel.
// = R16 (best: 31.49us) + L2 evict-first cache policy on the bulk copies:
// the 131MB stream is touched once, so default-allocate thrashes the 126MB
// L2; createpolicy.fractional.L2::evict_first + cp.async.bulk.L2::cache_hint
// marks fills as streaming. Everything else byte-identical to R16:
// grid 152 (full GB300), TMA prologue before counter zeroing, 4x32KB
// mbarrier pipeline, conflict-free u8 counters (word bank == lane for any
// key), integer atomicAdd joint histogram, ticketed finalize + reset.

#define NBATCH  4
#define NCLS    10
#define NKEY    (NCLS * NCLS)                 // 100
#define THREADS 512
#define CHUNKS_PER_BATCH 38
#define NBLK    (NBATCH * CHUNKS_PER_BATCH)   // 152 = 1 block per GB300 SM
#define STAGE_VECS 1024                       // int4 per tensor per stage (16KB)
#define NBUF    4

#define CNT_BYTES   (25 * 16 * 128)               // 51200
#define BUF_BYTES   (2 * STAGE_VECS * 16)         // 32768 per buffer
#define OFF_BUF     CNT_BYTES
#define OFF_MBAR    (CNT_BYTES + NBUF * BUF_BYTES)    // 182272
#define SMEM_BYTES  (OFF_MBAR + 64)

__device__ unsigned int g_joint[NBATCH * NKEY];  // zero-init; reset by last block
__device__ unsigned int g_done;                  // ticket; reset by last block

__device__ __forceinline__ uint32_t smem_u32(const void* p) {
    uint32_t a;
    asm("{ .reg .u64 t; cvta.to.shared.u64 t, %1; cvt.u32.u64 %0, t; }"
        : "=r"(a) : "l"(p));
    return a;
}
__device__ __forceinline__ void mbar_init(uint32_t a, uint32_t cnt) {
    asm volatile("mbarrier.init.shared::cta.b64 [%0], %1;" :: "r"(a), "r"(cnt) : "memory");
}
__device__ __forceinline__ void mbar_expect(uint32_t a, uint32_t bytes) {
    asm volatile("mbarrier.arrive.expect_tx.shared::cta.b64 _, [%0], %1;"
                 :: "r"(a), "r"(bytes) : "memory");
}
__device__ __forceinline__ uint64_t make_stream_policy() {
    uint64_t pol;
    asm volatile("createpolicy.fractional.L2::evict_first.b64 %0, 1.0;" : "=l"(pol));
    return pol;
}
__device__ __forceinline__ void bulk_g2s(uint32_t dst, const void* src,
                                         uint32_t bytes, uint32_t mbar,
                                         uint64_t pol) {
    asm volatile("cp.async.bulk.shared::cta.global.mbarrier::complete_tx::bytes"
                 ".L2::cache_hint [%0], [%1], %2, [%3], %4;"
                 :: "r"(dst), "l"(src), "r"(bytes), "r"(mbar), "l"(pol) : "memory");
}
__device__ __forceinline__ void mbar_wait(uint32_t a, uint32_t parity) {
    asm volatile(
        "{\n\t"
        ".reg .pred P;\n\t"
        "W_%=:\n\t"
        "mbarrier.try_wait.parity.acquire.cta.shared::cta.b64 P, [%0], %1, 0x989680;\n\t"
        "@P bra.uni D_%=;\n\t"
        "bra.uni W_%=;\n\t"
        "D_%=:\n\t"
        "}" :: "r"(a), "r"(parity) : "memory");
}

// Conflict-free u8 bump: base = cnt + wid*128 + lane*4 (per-thread const).
// off(k) = ((k & ~3) << 9) + (k & 3): word bank == lane for all k.
__device__ __forceinline__ void bump1(unsigned char* base, int p, int t) {
    int k = p * NCLS + t;
    base[((k & ~3) << 9) + (k & 3)] += 1;
}
__device__ __forceinline__ void bump(unsigned char* base, int4 p, int4 t) {
    bump1(base, p.x, t.x);
    bump1(base, p.y, t.y);
    bump1(base, p.z, t.z);
    bump1(base, p.w, t.w);
}

__global__ __launch_bounds__(THREADS, 1)
void dice_fused_kernel(const int4* __restrict__ yp,
                       const int4* __restrict__ yt,
                       int vecs_per_batch, int chunk,
                       float* __restrict__ out)
{
    extern __shared__ unsigned char smem_raw[];
    unsigned char* cnt = smem_raw;
    const int tid = threadIdx.x;
    const int wid = tid >> 5, lane = tid & 31;
    unsigned char* mybase = cnt + wid * 128 + lane * 4;
    const uint32_t smem_base = smem_u32(smem_raw);
    const uint32_t mbar0 = smem_base + OFF_MBAR;

    const int batch = blockIdx.x / CHUNKS_PER_BATCH;
    const int sub   = blockIdx.x % CHUNKS_PER_BATCH;
    const long base = (long)batch * vecs_per_batch;
    const int start = sub * chunk;
    const int end   = min(start + chunk, vecs_per_batch);
    const int span  = end - start;
    const int nst   = (span + STAGE_VECS - 1) / STAGE_VECS;

    // tid0: init mbarriers + launch first NBUF stages FIRST, so the bulk
    // copies run while all threads zero the 51.2KB counter array below.
    if (tid == 0) {
        uint64_t pol = make_stream_policy();
        #pragma unroll
        for (int b = 0; b < NBUF; b++)
            mbar_init(mbar0 + b * 8, 1);
        for (int s = 0; s < NBUF && s < nst; s++) {
            int b = s & (NBUF - 1);
            int ns = min(STAGE_VECS, span - s * STAGE_VECS);
            uint32_t bytes = (uint32_t)ns * 16u;
            uint32_t dp = smem_base + OFF_BUF + b * BUF_BYTES;
            uint32_t dt = dp + STAGE_VECS * 16;
            mbar_expect(mbar0 + b * 8, 2u * bytes);
            bulk_g2s(dp, yp + base + start + s * STAGE_VECS, bytes, mbar0 + b * 8, pol);
            bulk_g2s(dt, yt + base + start + s * STAGE_VECS, bytes, mbar0 + b * 8, pol);
        }
    }

    // Zero private counters (int4-vectorized) while TMA streams in.
    int4* smz = (int4*)cnt;
    #pragma unroll
    for (int i = tid; i < CNT_BYTES / 16; i += THREADS)
        smz[i] = make_int4(0, 0, 0, 0);
    __syncthreads();

    // Steady state: wait(s) -> consume(s) -> sync -> issue(s+NBUF).
    for (int s = 0; s < nst; s++) {
        int b = s & (NBUF - 1);
        mbar_wait(mbar0 + b * 8, (s >> 2) & 1);

        const int4* bp = (const int4*)(smem_raw + OFF_BUF + b * BUF_BYTES);
        const int4* bt = bp + STAGE_VECS;
        int ns = min(STAGE_VECS, span - s * STAGE_VECS);
        for (int j = tid; j < ns; j += THREADS)
            bump(mybase, bp[j], bt[j]);

        __syncthreads();   // buffer b fully consumed by all threads

        int f = s + NBUF;
        if (tid == 0 && f < nst) {
            uint64_t pol = make_stream_policy();
            int ns2 = min(STAGE_VECS, span - f * STAGE_VECS);
            uint32_t bytes = (uint32_t)ns2 * 16u;
            uint32_t dp = smem_base + OFF_BUF + b * BUF_BYTES;
            uint32_t dt = dp + STAGE_VECS * 16;
            mbar_expect(mbar0 + b * 8, 2u * bytes);
            bulk_g2s(dp, yp + base + start + f * STAGE_VECS, bytes, mbar0 + b * 8, pol);
            bulk_g2s(dt, yt + base + start + f * STAGE_VECS, bytes, mbar0 + b * 8, pol);
        }
    }
    __syncthreads();

    // Epilogue: warp w sums keys k = w, w+16, ... Count(k, thread(w2,l)) is
    // byte (k&3) of word ((k>>2)*16 + w2)*32 + l -> lane-indexed, no conflicts.
    const unsigned int* cnt32 = (const unsigned int*)cnt;
    for (int k = wid; k < NKEY; k += THREADS / 32) {
        int q = k >> 2, r = (k & 3) * 8;
        unsigned int s = 0;
        #pragma unroll
        for (int j = 0; j < 16; j++)
            s += (cnt32[(q * 16 + j) * 32 + lane] >> r) & 0xFFu;
        #pragma unroll
        for (int o = 16; o; o >>= 1)
            s += __shfl_down_sync(0xFFFFFFFFu, s, o);
        if (lane == 0)
            atomicAdd(&g_joint[batch * NKEY + k], s);   // integer: order-independent
    }

    // Last-block ticket.
    __threadfence();
    __shared__ bool is_last;
    if (tid == 0)
        is_last = (atomicAdd(&g_done, 1u) == NBLK - 1);
    __syncthreads();
    if (!is_last) return;
    __threadfence();

    // ---- Finalize from g_joint (L2-hot). Strided phases. ----
    __shared__ unsigned int J[NBATCH * NKEY];
    __shared__ float ctv[NBATCH * NCLS];
    __shared__ float terms[NBATCH * (NCLS - 1)];

    for (int x = tid; x < NBATCH * NKEY; x += THREADS)
        J[x] = g_joint[x];
    __syncthreads();

    for (int x = tid; x < NBATCH * NKEY; x += THREADS)
        g_joint[x] = 0u;
    if (tid == 0) g_done = 0u;

    for (int x = tid; x < NBATCH * NCLS; x += THREADS) {
        int bb = x / NCLS, c = x % NCLS;
        unsigned int ct = 0;
        #pragma unroll
        for (int p = 0; p < NCLS; p++)
            ct += J[bb * NKEY + p * NCLS + c];
        ctv[x] = (float)ct;
    }
    __syncthreads();

    for (int x = tid; x < NBATCH * (NCLS - 1); x += THREADS) {
        int bb = x / (NCLS - 1);
        int c = 1 + x % (NCLS - 1);
        unsigned int cp = 0;
        #pragma unroll
        for (int t = 0; t < NCLS; t++)
            cp += J[bb * NKEY + c * NCLS + t];
        float ct    = ctv[bb * NCLS + c];
        float inter = (float)J[bb * NKEY + c * NCLS + c];
        float denom = (float)cp + ct;
        float sumct = 0.0f;
        #pragma unroll
        for (int cc = 1; cc < NCLS; cc++)
            sumct += ctv[bb * NCLS + cc];
        float term = 0.0f;
        if (denom > 0.0f)
            term = (ct / sumct * (1.0f / NBATCH)) * (2.0f * inter / denom);
        terms[x] = term;
    }
    __syncthreads();

    if (tid == 0) {
        float tot = 0.0f;
        for (int i2 = 0; i2 < NBATCH * (NCLS - 1); i2++)
            tot += terms[i2];
        out[0] = 1.0f - tot;
    }
}

extern "C" void kernel_launch(void* const* d_in, const int* in_sizes, int n_in,
                              void* d_out, int out_size)
{
    const int4* yp = (const int4*)d_in[0];
    const int4* yt = (const int4*)d_in[1];
    float* out = (float*)d_out;

    int vecs_per_batch = in_sizes[0] / (NBATCH * 4);
    int chunk = (vecs_per_batch + CHUNKS_PER_BATCH - 1) / CHUNKS_PER_BATCH;

    cudaFuncSetAttribute(dice_fused_kernel,
                         cudaFuncAttributeMaxDynamicSharedMemorySize, SMEM_BYTES);

    dice_fused_kernel<<<NBLK, THREADS, SMEM_BYTES>>>(yp, yt, vecs_per_batch,
                                                     chunk, out);
    (void)n_in; (void)out_size;
}